// round 12
// baseline (speedup 1.0000x reference)
#include <cuda_runtime.h>

#define TT 11
#define THREADS 512
#define ITEMS 8
#define NW 16                            // warps per block
#define PER_BLOCK 4096
#define BMAX 8192
#define GRID 444                         // 3 x 148: co-resident on >=148 SMs at occ 3
#define SC_FLOATS (3 * PER_BLOCK + 64)   // staging + alignment padding

__device__ int g_blockHist[BMAX * 16];
__device__ int g_blockBase[BMAX * 16];   // includes type offset after scan
__device__ unsigned int g_ticket;        // monotonic across graph replays
__device__ unsigned int g_flag;          // monotonic generation counter

__device__ __forceinline__ int fieldOf(unsigned long long q0, unsigned long long q1, int t) {
    unsigned long long q = (t < 6) ? q0 : q1;
    int sh = (t < 6) ? 10 * t : 10 * (t - 6);
    return (int)((q >> sh) & 1023ull);
}

// per-block dtype detection: read int64 words; if data is int32 the hi half of
// each word is the next type value (nonzero w.p. 10/11 per sample).
__device__ __forceinline__ int detect64(const void* types, int N, int base) {
    const long long* t64 = (const long long*)types;
    int wmax = N >> 1;
    int wi = (base >> 1) + threadIdx.x;
    if (wi >= wmax) wi = wmax - 1;
    long long v = t64[wi];
    return __syncthreads_and(v >= 0 && v < TT);
}

// 8 types -> 2 packed-byte registers
__device__ __forceinline__ void loadTypes8(const void* types, int gbase, int is64,
                                           unsigned int tp[2]) {
    if (is64) {
        const longlong2* p = (const longlong2*)((const long long*)types + gbase);
        longlong2 a = p[0], b = p[1], c = p[2], d = p[3];
        tp[0] = (unsigned)a.x | ((unsigned)a.y << 8) |
                ((unsigned)b.x << 16) | ((unsigned)b.y << 24);
        tp[1] = (unsigned)c.x | ((unsigned)c.y << 8) |
                ((unsigned)d.x << 16) | ((unsigned)d.y << 24);
    } else {
        const int4* p = (const int4*)((const int*)types + gbase);
        int4 a = p[0], b = p[1];
        tp[0] = (unsigned)a.x | ((unsigned)a.y << 8) |
                ((unsigned)a.z << 16) | ((unsigned)a.w << 24);
        tp[1] = (unsigned)b.x | ((unsigned)b.y << 8) |
                ((unsigned)b.z << 16) | ((unsigned)b.w << 24);
    }
}

__device__ __forceinline__ int scalarType(const void* types, int i, int is64) {
    return is64 ? (int)((const long long*)types)[i] : ((const int*)types)[i];
}

// ---------------- fused persistent kernel: hist -> scan (1 block) -> scatter ----
__global__ void __launch_bounds__(THREADS, 3) k_fused(const float* __restrict__ coords,
                                                      const void* __restrict__ types,
                                                      float* __restrict__ out, int N, int T,
                                                      float* outTail, int writeTail) {
    extern __shared__ char smem[];
    unsigned long long* sW0 = (unsigned long long*)smem;       // @0   (8B aligned)
    unsigned long long* sW1 = sW0 + NW;                        // @128
    float* sC = (float*)(sW1 + NW);                            // @256 (16B aligned)
    int* sBase = (int*)(sC + SC_FLOATS);                       // TT*513 ints (read-only)
    int* sWB = sBase + TT * 513;                               // NW*16
    int* sTot = sWB + NW * 16;                                 // 16
    int* sLoc = sTot + 16;                                     // 16
    int* sGB3 = sLoc + 16;                                     // 16

    __shared__ int sCounts[16], sOff[16], sExcl[TT * 32];
    __shared__ int sIsLast;

    int tid = threadIdx.x, lane = tid & 31, w = tid >> 5;
    int blk = blockIdx.x;

    unsigned gen0 = ((volatile unsigned*)&g_flag)[0];   // entry read (pre-increment)

    // ================= phase A: histogram of my tiles =================
    for (int tile = blk; tile < T; tile += GRID) {
        int base = tile * PER_BLOCK;
        int is64 = detect64(types, N, base);
        int myBase = base + tid * ITEMS;
        unsigned long long p0 = 0, p1 = 0;
        if (base + PER_BLOCK <= N) {
            unsigned tp[2];
            loadTypes8(types, myBase, is64, tp);
#pragma unroll
            for (int j = 0; j < ITEMS; j++) {
                int t = (tp[j >> 2] >> ((j & 3) * 8)) & 0xFF;
                if (t < 6) p0 += 1ull << (10 * t); else p1 += 1ull << (10 * (t - 6));
            }
        } else {
            int cnt = N - myBase; cnt = cnt < 0 ? 0 : (cnt > ITEMS ? ITEMS : cnt);
            for (int j = 0; j < cnt; j++) {
                int t = scalarType(types, myBase + j, is64);
                if (t < 6) p0 += 1ull << (10 * t); else p1 += 1ull << (10 * (t - 6));
            }
        }
#pragma unroll
        for (int d = 16; d; d >>= 1) {
            p0 += __shfl_xor_sync(0xffffffffu, p0, d);
            p1 += __shfl_xor_sync(0xffffffffu, p1, d);
        }
        if (lane == 0) { sW0[w] = p0; sW1[w] = p1; }
        __syncthreads();
        if (tid < TT) {
            int s = 0;
#pragma unroll
            for (int ww = 0; ww < NW; ww++) s += fieldOf(sW0[ww], sW1[ww], tid);
            g_blockHist[tile * 16 + tid] = s;
        }
        __syncthreads();   // protect sW0/sW1 reuse next tile
    }

    // ================= ticket; last arriver scans =================
    if (tid == 0) {
        __threadfence();
        unsigned tk = atomicAdd(&g_ticket, 1u);
        sIsLast = (((tk + 1u) % (unsigned)GRID) == 0u);
    }
    __syncthreads();
    if (sIsLast) {
        __threadfence();   // make all blocks' hist writes visible
        int chunk = (T + 31) / 32;
        int s0 = lane * chunk;
        int cnt = T - s0; cnt = cnt < 0 ? 0 : (cnt > chunk ? chunk : cnt);
        for (int tt = w; tt < TT; tt += NW) {
            int sum = 0;
            for (int j = 0; j < cnt; j++) sum += g_blockHist[(s0 + j) * 16 + tt];
            int inc = sum;
#pragma unroll
            for (int d = 1; d < 32; d <<= 1) {
                int n = __shfl_up_sync(0xffffffffu, inc, d);
                if (lane >= d) inc += n;
            }
            sExcl[tt * 32 + lane] = inc - sum;
            if (lane == 31) sCounts[tt] = inc;
        }
        __syncthreads();
        if (tid == 0) {
            int run = 0;
            for (int t = 0; t < TT; t++) {
                int c = sCounts[t];
                sOff[t] = run;
                if (writeTail) { outTail[t] = (float)c; outTail[TT + t] = (float)run; }
                run += c;
            }
        }
        __syncthreads();
        for (int tt = w; tt < TT; tt += NW) {
            int run = sOff[tt] + sExcl[tt * 32 + lane];
            for (int j = 0; j < cnt; j++) {
                int v = g_blockHist[(s0 + j) * 16 + tt];
                g_blockBase[(s0 + j) * 16 + tt] = run;
                run += v;
            }
        }
        __syncthreads();
        if (tid == 0) {
            __threadfence();               // release bases before flag bump
            atomicAdd(&g_flag, 1u);
        }
    }

    // ================= spin until scan generation advances =================
    if (tid == 0) {
        while (((volatile unsigned*)&g_flag)[0] == gen0) __nanosleep(200);
    }
    __syncthreads();

    // ================= phase B: scatter my tiles =================
    for (int tile = blk; tile < T; tile += GRID) {
        int base = tile * PER_BLOCK;
        int nblk = min(PER_BLOCK, N - base);
        int is64 = detect64(types, N, base);

        if (tid < TT) sGB3[tid] = g_blockBase[tile * 16 + tid] * 3;

        int myBase = tid * ITEMS;
        int myCnt = nblk - myBase; myCnt = myCnt < 0 ? 0 : (myCnt > ITEMS ? ITEMS : myCnt);
        bool full = (myCnt == ITEMS);

        unsigned tp[2];
        if (full) {
            loadTypes8(types, base + myBase, is64, tp);   // L2-hot after phase A
        } else {
            tp[0] = tp[1] = 0;
            for (int j = 0; j < myCnt; j++)
                tp[j >> 2] |= (unsigned)scalarType(types, base + myBase + j, is64) << ((j & 3) * 8);
        }

        // packed histogram + pre-increment nibble ranks
        unsigned long long p0 = 0, p1 = 0;
        unsigned rk = 0;
#pragma unroll
        for (int j = 0; j < ITEMS; j++) {
            if (j < myCnt) {
                int t = (tp[j >> 2] >> ((j & 3) * 8)) & 0xFF;
                int sh10 = (t < 6) ? 10 * t : 10 * (t - 6);
                unsigned long long q = (t < 6) ? p0 : p1;
                rk |= (unsigned)((q >> sh10) & 15ull) << (4 * j);
                if (t < 6) p0 += 1ull << sh10; else p1 += 1ull << sh10;
            }
        }
        unsigned long long m0 = p0, m1 = p1;
#pragma unroll
        for (int d = 1; d < 32; d <<= 1) {
            unsigned long long n0 = __shfl_up_sync(0xffffffffu, p0, d);
            unsigned long long n1 = __shfl_up_sync(0xffffffffu, p1, d);
            if (lane >= d) { p0 += n0; p1 += n1; }
        }
        unsigned long long e0 = p0 - m0, e1 = p1 - m1;
        if (lane == 31) { sW0[w] = p0; sW1[w] = p1; }
        __syncthreads();
        if (tid < TT) {
            int run = 0;
#pragma unroll
            for (int ww = 0; ww < NW; ww++) {
                sWB[ww * 16 + tid] = run;
                run += fieldOf(sW0[ww], sW1[ww], tid);
            }
            sTot[tid] = run;
        }
        __syncthreads();
        if (tid == 0) {
            // staged segment starts congruent mod 4 with global float bases
            int pos = sGB3[0] & 3;
            for (int t = 0; t < TT; t++) {
                pos += (sGB3[t] - pos) & 3;
                sLoc[t] = pos;
                pos += 3 * sTot[t];
            }
        }
        __syncthreads();
#pragma unroll
        for (int t = 0; t < TT; t++)
            sBase[t * 513 + tid] = sLoc[t] + 3 * (sWB[w * 16 + t] + fieldOf(e0, e1, t));
        __syncthreads();

        // replay in 2 chunks of 4 items: JIT coord loads, read-only slot lookup
#pragma unroll
        for (int c = 0; c < 2; c++) {
            float cz[12];
            if (full) {
                const float4* cp = (const float4*)(coords + (size_t)3 * (base + myBase) + 12 * c);
                float4 v0 = cp[0], v1 = cp[1], v2 = cp[2];
                cz[0] = v0.x; cz[1] = v0.y; cz[2] = v0.z; cz[3] = v0.w;
                cz[4] = v1.x; cz[5] = v1.y; cz[6] = v1.z; cz[7] = v1.w;
                cz[8] = v2.x; cz[9] = v2.y; cz[10] = v2.z; cz[11] = v2.w;
            } else {
                const float* cp = coords + (size_t)3 * (base + myBase) + 12 * c;
                int avail = 3 * myCnt - 12 * c;
#pragma unroll
                for (int i = 0; i < 12; i++) cz[i] = (i < avail) ? cp[i] : 0.0f;
            }
#pragma unroll
            for (int j2 = 0; j2 < 4; j2++) {
                int j = 4 * c + j2;
                if (j < myCnt) {
                    int t = (tp[j >> 2] >> ((j & 3) * 8)) & 0xFF;
                    int nib = (int)((rk >> (4 * j)) & 15u);
                    int r = sBase[t * 513 + tid] + 3 * nib;
                    sC[r + 0] = cz[3 * j2 + 0];
                    sC[r + 1] = cz[3 * j2 + 1];
                    sC[r + 2] = cz[3 * j2 + 2];
                }
            }
        }
        __syncthreads();

        // copy-out per type: <=3 scalar head, float4 body, <=3 scalar tail
        for (int t = 0; t < TT; t++) {
            int cnt3 = sTot[t] * 3;
            if (cnt3 == 0) continue;
            int gb = sGB3[t];
            int sb = sLoc[t];
            int head = (4 - (gb & 3)) & 3;
            head = head < cnt3 ? head : cnt3;
            if (tid < head) out[(size_t)gb + tid] = sC[sb + tid];
            int rem = cnt3 - head;
            int nvec = rem >> 2;
            const float4* s4 = (const float4*)(sC + sb + head);
            float4* g4 = (float4*)(out + gb + head);
            for (int i = tid; i < nvec; i += THREADS) g4[i] = s4[i];
            int tail = rem & 3;
            int done = head + 4 * nvec;
            if (tid < tail) out[(size_t)gb + done + tid] = sC[sb + done + tid];
        }
        __syncthreads();   // protect smem reuse next tile
    }
}

extern "C" void kernel_launch(void* const* d_in, const int* in_sizes, int n_in,
                              void* d_out, int out_size) {
    const float* coords = (const float*)d_in[0];
    const void* types = d_in[1];
    int N = in_sizes[1];
    int T = (N + PER_BLOCK - 1) / PER_BLOCK;
    float* out = (float*)d_out;
    long long coordsOut = (long long)3 * N;
    int writeTail = ((long long)out_size >= coordsOut + 2 * TT) ? 1 : 0;

    const int SMEM = 73472;
    cudaFuncSetAttribute(k_fused, cudaFuncAttributeMaxDynamicSharedMemorySize, SMEM);

    k_fused<<<GRID, THREADS, SMEM>>>(coords, types, out, N, T,
                                     out + coordsOut, writeTail);
}

// round 13
// speedup vs baseline: 1.1290x; 1.1290x over previous
#include <cuda_runtime.h>

#define TT 11
#define THREADS 512
#define ITEMS 12
#define NW 16                            // warps per block
#define PER_BLOCK 6144
#define BMAX 8192
#define SC_FLOATS (3 * PER_BLOCK + 64)   // staging + alignment padding

__device__ int g_blockHist[BMAX * 16];
__device__ int g_blockBase[BMAX * 16];   // includes type offset after scan
__device__ unsigned int g_ticket;        // monotonic across graph replays
__device__ int g_is64;                   // dtype flag, set by hist block 0

__device__ __forceinline__ int fieldOf(unsigned long long q0, unsigned long long q1, int t) {
    unsigned long long q = (t < 6) ? q0 : q1;
    int sh = (t < 6) ? 10 * t : 10 * (t - 6);
    return (int)((q >> sh) & 1023ull);
}

// per-block dtype detection: read int64 words; if data is int32 the hi half of
// each word is the next type value (nonzero w.p. 10/11 per sample).
__device__ __forceinline__ int detect64(const void* types, int N, int base) {
    const long long* t64 = (const long long*)types;
    int wmax = N >> 1;
    int wi = (base >> 1) + threadIdx.x;
    if (wi >= wmax) wi = wmax - 1;
    long long v = t64[wi];
    return __syncthreads_and(v >= 0 && v < TT);
}

// 12 types -> 3 packed-byte registers
__device__ __forceinline__ void loadTypes12(const void* types, int gbase, int is64,
                                            unsigned int tp[3]) {
    if (is64) {
        const longlong2* p = (const longlong2*)((const long long*)types + gbase);
#pragma unroll
        for (int k = 0; k < 3; k++) {
            longlong2 a = p[2 * k], b = p[2 * k + 1];
            tp[k] = (unsigned)a.x | ((unsigned)a.y << 8) |
                    ((unsigned)b.x << 16) | ((unsigned)b.y << 24);
        }
    } else {
        const int4* p = (const int4*)((const int*)types + gbase);
#pragma unroll
        for (int k = 0; k < 3; k++) {
            int4 a = p[k];
            tp[k] = (unsigned)a.x | ((unsigned)a.y << 8) |
                    ((unsigned)a.z << 16) | ((unsigned)a.w << 24);
        }
    }
}

__device__ __forceinline__ int scalarType(const void* types, int i, int is64) {
    return is64 ? (int)((const long long*)types)[i] : ((const int*)types)[i];
}

// -------- pass 1: per-block histogram; LAST block performs the global scan ------
__global__ void __launch_bounds__(THREADS) k_histscan(const void* __restrict__ types,
                                                      int N, int B,
                                                      float* outTail, int writeTail) {
    __shared__ unsigned long long sW0[NW], sW1[NW];
    __shared__ int sCounts[16], sOff[16], sExcl[TT * 32];
    __shared__ int sIsLast;
    int tid = threadIdx.x, lane = tid & 31, w = tid >> 5;
    int base = blockIdx.x * PER_BLOCK;
    int is64 = detect64(types, N, base);
    if (blockIdx.x == 0 && tid == 0) g_is64 = is64;

    int myBase = base + tid * ITEMS;
    unsigned long long p0 = 0, p1 = 0;
    if (base + PER_BLOCK <= N) {
        unsigned tp[3];
        loadTypes12(types, myBase, is64, tp);
#pragma unroll
        for (int j = 0; j < ITEMS; j++) {
            int t = (tp[j >> 2] >> ((j & 3) * 8)) & 0xFF;
            if (t < 6) p0 += 1ull << (10 * t); else p1 += 1ull << (10 * (t - 6));
        }
    } else {
        int cnt = N - myBase; cnt = cnt < 0 ? 0 : (cnt > ITEMS ? ITEMS : cnt);
        for (int j = 0; j < cnt; j++) {
            int t = scalarType(types, myBase + j, is64);
            if (t < 6) p0 += 1ull << (10 * t); else p1 += 1ull << (10 * (t - 6));
        }
    }
#pragma unroll
    for (int d = 16; d; d >>= 1) {
        p0 += __shfl_xor_sync(0xffffffffu, p0, d);
        p1 += __shfl_xor_sync(0xffffffffu, p1, d);
    }
    if (lane == 0) { sW0[w] = p0; sW1[w] = p1; }
    __syncthreads();
    if (tid < TT) {
        int s = 0;
#pragma unroll
        for (int ww = 0; ww < NW; ww++) s += fieldOf(sW0[ww], sW1[ww], tid);
        g_blockHist[blockIdx.x * 16 + tid] = s;
    }
    __syncthreads();
    if (tid == 0) {
        __threadfence();
        unsigned tk = atomicAdd(&g_ticket, 1u);
        sIsLast = (((tk + 1u) % (unsigned)B) == 0u);
    }
    __syncthreads();
    if (!sIsLast) return;

    __threadfence();   // acquire
    int chunk = (B + 31) / 32;
    int s0 = lane * chunk;
    int cnt = B - s0; cnt = cnt < 0 ? 0 : (cnt > chunk ? chunk : cnt);
    for (int tt = w; tt < TT; tt += NW) {
        int sum = 0;
        for (int j = 0; j < cnt; j++) sum += g_blockHist[(s0 + j) * 16 + tt];
        int inc = sum;
#pragma unroll
        for (int d = 1; d < 32; d <<= 1) {
            int n = __shfl_up_sync(0xffffffffu, inc, d);
            if (lane >= d) inc += n;
        }
        sExcl[tt * 32 + lane] = inc - sum;
        if (lane == 31) sCounts[tt] = inc;
    }
    __syncthreads();
    if (tid == 0) {
        int run = 0;
        for (int t = 0; t < TT; t++) {
            int c = sCounts[t];
            sOff[t] = run;
            if (writeTail) { outTail[t] = (float)c; outTail[TT + t] = (float)run; }
            run += c;
        }
    }
    __syncthreads();
    for (int tt = w; tt < TT; tt += NW) {
        int run = sOff[tt] + sExcl[tt * 32 + lane];
        for (int j = 0; j < cnt; j++) {
            int v = g_blockHist[(s0 + j) * 16 + tt];
            g_blockBase[(s0 + j) * 16 + tt] = run;
            run += v;
        }
    }
}

// -------- pass 2: 512 threads x 12 items; chain-free replay + aligned staging ---
__global__ void __launch_bounds__(THREADS, 2) k_scatter(const float* __restrict__ coords,
                                                        const void* __restrict__ types,
                                                        float* __restrict__ out, int N) {
    extern __shared__ char smem[];
    unsigned long long* sW0 = (unsigned long long*)smem;       // @0   (8B aligned)
    unsigned long long* sW1 = sW0 + NW;                        // @128
    float* sC = (float*)(sW1 + NW);                            // @256 (16B aligned)
    int* sBase = (int*)(sC + SC_FLOATS);                       // TT*513 ints (read-only)
    int* sWB = sBase + TT * 513;                               // NW*16
    int* sTot = sWB + NW * 16;                                 // 16
    int* sLoc = sTot + 16;                                     // 16
    int* sGB3 = sLoc + 16;                                     // 16
    // total = 256 + 73984 + 22572 + 1024 + 192 = 98028 -> 98048

    int tid = threadIdx.x, lane = tid & 31, w = tid >> 5;
    int blk = blockIdx.x, base = blk * PER_BLOCK;
    int nblk = min(PER_BLOCK, N - base);
    int is64 = g_is64;   // set by k_histscan (previous launch)

    if (tid < TT) sGB3[tid] = g_blockBase[blk * 16 + tid] * 3;

    int myBase = tid * ITEMS;
    int myCnt = nblk - myBase; myCnt = myCnt < 0 ? 0 : (myCnt > ITEMS ? ITEMS : myCnt);
    bool full = (myCnt == ITEMS);

    unsigned tp[3];
    if (full) {
        loadTypes12(types, base + myBase, is64, tp);   // L2-hot after hist pass
    } else {
        tp[0] = tp[1] = tp[2] = 0;
        for (int j = 0; j < myCnt; j++)
            tp[j >> 2] |= (unsigned)scalarType(types, base + myBase + j, is64) << ((j & 3) * 8);
    }

    // per-thread packed histogram; capture each item's PRE-increment count as a
    // 4-bit nibble (within-thread-per-type rank, <=11 fits).
    unsigned long long p0 = 0, p1 = 0, rk = 0;
#pragma unroll
    for (int j = 0; j < ITEMS; j++) {
        if (j < myCnt) {
            int t = (tp[j >> 2] >> ((j & 3) * 8)) & 0xFF;
            int sh10 = (t < 6) ? 10 * t : 10 * (t - 6);
            unsigned long long q = (t < 6) ? p0 : p1;
            rk |= ((q >> sh10) & 15ull) << (4 * j);
            if (t < 6) p0 += 1ull << sh10; else p1 += 1ull << sh10;
        }
    }
    unsigned long long m0 = p0, m1 = p1;
#pragma unroll
    for (int d = 1; d < 32; d <<= 1) {
        unsigned long long n0 = __shfl_up_sync(0xffffffffu, p0, d);
        unsigned long long n1 = __shfl_up_sync(0xffffffffu, p1, d);
        if (lane >= d) { p0 += n0; p1 += n1; }
    }
    unsigned long long e0 = p0 - m0, e1 = p1 - m1;   // exclusive within warp
    if (lane == 31) { sW0[w] = p0; sW1[w] = p1; }
    __syncthreads();
    if (tid < TT) {
        int run = 0;
#pragma unroll
        for (int ww = 0; ww < NW; ww++) {
            sWB[ww * 16 + tid] = run;
            run += fieldOf(sW0[ww], sW1[ww], tid);
        }
        sTot[tid] = run;
    }
    __syncthreads();
    if (tid == 0) {
        // staged segment starts congruent mod 4 with global float bases so the
        // copy-out can use LDS.128/STG.128 after a <=3 float head
        int pos = sGB3[0] & 3;
        for (int t = 0; t < TT; t++) {
            pos += (sGB3[t] - pos) & 3;
            sLoc[t] = pos;
            pos += 3 * sTot[t];
        }
    }
    __syncthreads();

    // per-thread per-type START positions (staged float units); READ-ONLY after.
    // stride 513 ints: bank (513t+tid)%32 = (t+tid)%32 -> conflict-free per warp
#pragma unroll
    for (int t = 0; t < TT; t++)
        sBase[t * 513 + tid] = sLoc[t] + 3 * (sWB[w * 16 + t] + fieldOf(e0, e1, t));
    __syncthreads();

    // replay in 3 chunks of 4 items: JIT coord loads; slots are independent.
#pragma unroll
    for (int c = 0; c < 3; c++) {
        float cz[12];
        if (full) {
            const float4* cp = (const float4*)(coords + (size_t)3 * (base + myBase) + 12 * c);
            float4 v0 = cp[0], v1 = cp[1], v2 = cp[2];
            cz[0] = v0.x; cz[1] = v0.y; cz[2] = v0.z; cz[3] = v0.w;
            cz[4] = v1.x; cz[5] = v1.y; cz[6] = v1.z; cz[7] = v1.w;
            cz[8] = v2.x; cz[9] = v2.y; cz[10] = v2.z; cz[11] = v2.w;
        } else {
            const float* cp = coords + (size_t)3 * (base + myBase) + 12 * c;
            int avail = 3 * myCnt - 12 * c;
#pragma unroll
            for (int i = 0; i < 12; i++) cz[i] = (i < avail) ? cp[i] : 0.0f;
        }
#pragma unroll
        for (int j2 = 0; j2 < 4; j2++) {
            int j = 4 * c + j2;
            if (j < myCnt) {
                int t = (tp[j >> 2] >> ((j & 3) * 8)) & 0xFF;
                int nib = (int)((rk >> (4 * j)) & 15ull);
                int r = sBase[t * 513 + tid] + 3 * nib;   // read-only lookup
                sC[r + 0] = cz[3 * j2 + 0];
                sC[r + 1] = cz[3 * j2 + 1];
                sC[r + 2] = cz[3 * j2 + 2];
            }
        }
    }
    __syncthreads();

    // copy-out per type: <=3 scalar head, float4 body, <=3 scalar tail
    for (int t = 0; t < TT; t++) {
        int cnt3 = sTot[t] * 3;
        if (cnt3 == 0) continue;
        int gb = sGB3[t];
        int sb = sLoc[t];
        int head = (4 - (gb & 3)) & 3;
        head = head < cnt3 ? head : cnt3;
        if (tid < head) out[(size_t)gb + tid] = sC[sb + tid];
        int rem = cnt3 - head;
        int nvec = rem >> 2;
        const float4* s4 = (const float4*)(sC + sb + head);
        float4* g4 = (float4*)(out + gb + head);
        for (int i = tid; i < nvec; i += THREADS) g4[i] = s4[i];
        int tail = rem & 3;
        int done = head + 4 * nvec;
        if (tid < tail) out[(size_t)gb + done + tid] = sC[sb + done + tid];
    }
}

extern "C" void kernel_launch(void* const* d_in, const int* in_sizes, int n_in,
                              void* d_out, int out_size) {
    const float* coords = (const float*)d_in[0];
    const void* types = d_in[1];
    int N = in_sizes[1];
    int B = (N + PER_BLOCK - 1) / PER_BLOCK;
    float* out = (float*)d_out;
    long long coordsOut = (long long)3 * N;
    int writeTail = ((long long)out_size >= coordsOut + 2 * TT) ? 1 : 0;

    const int SMEM = 98048;
    cudaFuncSetAttribute(k_scatter, cudaFuncAttributeMaxDynamicSharedMemorySize, SMEM);

    k_histscan<<<B, THREADS>>>(types, N, B, out + coordsOut, writeTail);
    k_scatter<<<B, THREADS, SMEM>>>(coords, types, out, N);
}

// round 14
// speedup vs baseline: 1.1949x; 1.0584x over previous
#include <cuda_runtime.h>

#define TT 11
#define THREADS 512
#define ITEMS 12
#define NW 16                            // warps per block
#define PER_BLOCK 6144
#define BMAX 8192
#define SC_FLOATS (3 * PER_BLOCK + 64)   // staging + alignment padding

__device__ int g_blockHist[BMAX * 16];
__device__ int g_blockBase[BMAX * 16];   // includes type offset after scan
__device__ unsigned int g_ticket;        // monotonic across graph replays
__device__ int g_is64;                   // dtype flag, set by hist block 0

__device__ __forceinline__ int fieldOf(unsigned long long q0, unsigned long long q1, int t) {
    unsigned long long q = (t < 6) ? q0 : q1;
    int sh = (t < 6) ? 10 * t : 10 * (t - 6);
    return (int)((q >> sh) & 1023ull);
}

// per-block dtype detection: read int64 words; if data is int32 the hi half of
// each word is the next type value (nonzero w.p. 10/11 per sample).
__device__ __forceinline__ int detect64(const void* types, int N, int base) {
    const long long* t64 = (const long long*)types;
    int wmax = N >> 1;
    int wi = (base >> 1) + threadIdx.x;
    if (wi >= wmax) wi = wmax - 1;
    long long v = t64[wi];
    return __syncthreads_and(v >= 0 && v < TT);
}

// 12 types -> 3 packed-byte registers
__device__ __forceinline__ void loadTypes12(const void* types, int gbase, int is64,
                                            unsigned int tp[3]) {
    if (is64) {
        const longlong2* p = (const longlong2*)((const long long*)types + gbase);
#pragma unroll
        for (int k = 0; k < 3; k++) {
            longlong2 a = p[2 * k], b = p[2 * k + 1];
            tp[k] = (unsigned)a.x | ((unsigned)a.y << 8) |
                    ((unsigned)b.x << 16) | ((unsigned)b.y << 24);
        }
    } else {
        const int4* p = (const int4*)((const int*)types + gbase);
#pragma unroll
        for (int k = 0; k < 3; k++) {
            int4 a = p[k];
            tp[k] = (unsigned)a.x | ((unsigned)a.y << 8) |
                    ((unsigned)a.z << 16) | ((unsigned)a.w << 24);
        }
    }
}

__device__ __forceinline__ int scalarType(const void* types, int i, int is64) {
    return is64 ? (int)((const long long*)types)[i] : ((const int*)types)[i];
}

// -------- pass 1: per-block histogram; LAST block performs the global scan ------
__global__ void __launch_bounds__(THREADS) k_histscan(const void* __restrict__ types,
                                                      int N, int B,
                                                      float* outTail, int writeTail) {
    __shared__ unsigned long long sW0[NW], sW1[NW];
    __shared__ int sCounts[16], sOff[16], sExcl[TT * 32];
    __shared__ int sIsLast;
    int tid = threadIdx.x, lane = tid & 31, w = tid >> 5;
    int base = blockIdx.x * PER_BLOCK;
    int is64 = detect64(types, N, base);
    if (blockIdx.x == 0 && tid == 0) g_is64 = is64;

    int myBase = base + tid * ITEMS;
    unsigned long long p0 = 0, p1 = 0;
    if (base + PER_BLOCK <= N) {
        unsigned tp[3];
        loadTypes12(types, myBase, is64, tp);
#pragma unroll
        for (int j = 0; j < ITEMS; j++) {
            int t = (tp[j >> 2] >> ((j & 3) * 8)) & 0xFF;
            if (t < 6) p0 += 1ull << (10 * t); else p1 += 1ull << (10 * (t - 6));
        }
    } else {
        int cnt = N - myBase; cnt = cnt < 0 ? 0 : (cnt > ITEMS ? ITEMS : cnt);
        for (int j = 0; j < cnt; j++) {
            int t = scalarType(types, myBase + j, is64);
            if (t < 6) p0 += 1ull << (10 * t); else p1 += 1ull << (10 * (t - 6));
        }
    }
#pragma unroll
    for (int d = 16; d; d >>= 1) {
        p0 += __shfl_xor_sync(0xffffffffu, p0, d);
        p1 += __shfl_xor_sync(0xffffffffu, p1, d);
    }
    if (lane == 0) { sW0[w] = p0; sW1[w] = p1; }
    __syncthreads();
    if (tid < TT) {
        int s = 0;
#pragma unroll
        for (int ww = 0; ww < NW; ww++) s += fieldOf(sW0[ww], sW1[ww], tid);
        g_blockHist[blockIdx.x * 16 + tid] = s;
    }
    __syncthreads();
    if (tid == 0) {
        __threadfence();
        unsigned tk = atomicAdd(&g_ticket, 1u);
        sIsLast = (((tk + 1u) % (unsigned)B) == 0u);
    }
    __syncthreads();
    if (!sIsLast) return;

    __threadfence();   // acquire
    int chunk = (B + 31) / 32;
    int s0 = lane * chunk;
    int cnt = B - s0; cnt = cnt < 0 ? 0 : (cnt > chunk ? chunk : cnt);
    for (int tt = w; tt < TT; tt += NW) {
        int sum = 0;
        for (int j = 0; j < cnt; j++) sum += g_blockHist[(s0 + j) * 16 + tt];
        int inc = sum;
#pragma unroll
        for (int d = 1; d < 32; d <<= 1) {
            int n = __shfl_up_sync(0xffffffffu, inc, d);
            if (lane >= d) inc += n;
        }
        sExcl[tt * 32 + lane] = inc - sum;
        if (lane == 31) sCounts[tt] = inc;
    }
    __syncthreads();
    if (tid == 0) {
        int run = 0;
        for (int t = 0; t < TT; t++) {
            int c = sCounts[t];
            sOff[t] = run;
            if (writeTail) { outTail[t] = (float)c; outTail[TT + t] = (float)run; }
            run += c;
        }
    }
    __syncthreads();
    for (int tt = w; tt < TT; tt += NW) {
        int run = sOff[tt] + sExcl[tt * 32 + lane];
        for (int j = 0; j < cnt; j++) {
            int v = g_blockHist[(s0 + j) * 16 + tt];
            g_blockBase[(s0 + j) * 16 + tt] = run;
            run += v;
        }
    }
}

// -------- pass 2: coords prefetched at entry (latency hidden behind the rank
//          phases) + chain-free replay + aligned staging + float4 copy-out -----
__global__ void __launch_bounds__(THREADS, 2) k_scatter(const float* __restrict__ coords,
                                                        const void* __restrict__ types,
                                                        float* __restrict__ out, int N) {
    extern __shared__ char smem[];
    unsigned long long* sW0 = (unsigned long long*)smem;       // @0   (8B aligned)
    unsigned long long* sW1 = sW0 + NW;                        // @128
    float* sC = (float*)(sW1 + NW);                            // @256 (16B aligned)
    int* sBase = (int*)(sC + SC_FLOATS);                       // TT*513 ints (read-only)
    int* sWB = sBase + TT * 513;                               // NW*16
    int* sTot = sWB + NW * 16;                                 // 16
    int* sLoc = sTot + 16;                                     // 16
    int* sGB3 = sLoc + 16;                                     // 16

    int tid = threadIdx.x, lane = tid & 31, w = tid >> 5;
    int blk = blockIdx.x, base = blk * PER_BLOCK;
    int nblk = min(PER_BLOCK, N - base);
    int is64 = g_is64;   // set by k_histscan (previous launch)

    if (tid < TT) sGB3[tid] = g_blockBase[blk * 16 + tid] * 3;

    int myBase = tid * ITEMS;
    int myCnt = nblk - myBase; myCnt = myCnt < 0 ? 0 : (myCnt > ITEMS ? ITEMS : myCnt);
    bool full = (myCnt == ITEMS);

    // ---- PREFETCH: issue ALL coord + type loads up-front; the entire rank
    //      computation below becomes the latency-hiding buffer. ----
    float4 pf[9];
    unsigned tp[3];
    if (full) {
        const float4* cp = (const float4*)(coords + (size_t)3 * (base + myBase));
#pragma unroll
        for (int k = 0; k < 9; k++) pf[k] = cp[k];
        loadTypes12(types, base + myBase, is64, tp);   // L2-hot after hist pass
    } else {
        tp[0] = tp[1] = tp[2] = 0;
        for (int j = 0; j < myCnt; j++)
            tp[j >> 2] |= (unsigned)scalarType(types, base + myBase + j, is64) << ((j & 3) * 8);
        const float* cp = coords + (size_t)3 * (base + myBase);
#pragma unroll
        for (int k = 0; k < 9; k++) {
            float x = 0, y = 0, z = 0, ww2 = 0;
            int o = 4 * k;
            if (o + 0 < 3 * myCnt) x = cp[o + 0];
            if (o + 1 < 3 * myCnt) y = cp[o + 1];
            if (o + 2 < 3 * myCnt) z = cp[o + 2];
            if (o + 3 < 3 * myCnt) ww2 = cp[o + 3];
            pf[k] = make_float4(x, y, z, ww2);
        }
    }

    // per-thread packed histogram; capture each item's PRE-increment count as a
    // 4-bit nibble (within-thread-per-type rank, <=11 fits).
    unsigned long long p0 = 0, p1 = 0, rk = 0;
#pragma unroll
    for (int j = 0; j < ITEMS; j++) {
        if (j < myCnt) {
            int t = (tp[j >> 2] >> ((j & 3) * 8)) & 0xFF;
            int sh10 = (t < 6) ? 10 * t : 10 * (t - 6);
            unsigned long long q = (t < 6) ? p0 : p1;
            rk |= ((q >> sh10) & 15ull) << (4 * j);
            if (t < 6) p0 += 1ull << sh10; else p1 += 1ull << sh10;
        }
    }
    unsigned long long m0 = p0, m1 = p1;
#pragma unroll
    for (int d = 1; d < 32; d <<= 1) {
        unsigned long long n0 = __shfl_up_sync(0xffffffffu, p0, d);
        unsigned long long n1 = __shfl_up_sync(0xffffffffu, p1, d);
        if (lane >= d) { p0 += n0; p1 += n1; }
    }
    unsigned long long e0 = p0 - m0, e1 = p1 - m1;   // exclusive within warp
    if (lane == 31) { sW0[w] = p0; sW1[w] = p1; }
    __syncthreads();
    if (tid < TT) {
        int run = 0;
#pragma unroll
        for (int ww = 0; ww < NW; ww++) {
            sWB[ww * 16 + tid] = run;
            run += fieldOf(sW0[ww], sW1[ww], tid);
        }
        sTot[tid] = run;
    }
    __syncthreads();
    if (tid == 0) {
        // staged segment starts congruent mod 4 with global float bases so the
        // copy-out can use LDS.128/STG.128 after a <=3 float head
        int pos = sGB3[0] & 3;
        for (int t = 0; t < TT; t++) {
            pos += (sGB3[t] - pos) & 3;
            sLoc[t] = pos;
            pos += 3 * sTot[t];
        }
    }
    __syncthreads();

    // per-thread per-type START positions (staged float units); READ-ONLY after.
    // stride 513 ints: bank (513t+tid)%32 = (t+tid)%32 -> conflict-free per warp
#pragma unroll
    for (int t = 0; t < TT; t++)
        sBase[t * 513 + tid] = sLoc[t] + 3 * (sWB[w * 16 + t] + fieldOf(e0, e1, t));
    __syncthreads();

    // replay: coords already in registers -> no load stalls; slots independent.
#pragma unroll
    for (int j = 0; j < ITEMS; j++) {
        if (j < myCnt) {
            int t = (tp[j >> 2] >> ((j & 3) * 8)) & 0xFF;
            int nib = (int)((rk >> (4 * j)) & 15ull);
            int r = sBase[t * 513 + tid] + 3 * nib;   // read-only lookup
            const float* f = (const float*)pf;
            sC[r + 0] = f[3 * j + 0];
            sC[r + 1] = f[3 * j + 1];
            sC[r + 2] = f[3 * j + 2];
        }
    }
    __syncthreads();

    // copy-out per type: <=3 scalar head, float4 body, <=3 scalar tail
    for (int t = 0; t < TT; t++) {
        int cnt3 = sTot[t] * 3;
        if (cnt3 == 0) continue;
        int gb = sGB3[t];
        int sb = sLoc[t];
        int head = (4 - (gb & 3)) & 3;
        head = head < cnt3 ? head : cnt3;
        if (tid < head) out[(size_t)gb + tid] = sC[sb + tid];
        int rem = cnt3 - head;
        int nvec = rem >> 2;
        const float4* s4 = (const float4*)(sC + sb + head);
        float4* g4 = (float4*)(out + gb + head);
        for (int i = tid; i < nvec; i += THREADS) g4[i] = s4[i];
        int tail = rem & 3;
        int done = head + 4 * nvec;
        if (tid < tail) out[(size_t)gb + done + tid] = sC[sb + done + tid];
    }
}

extern "C" void kernel_launch(void* const* d_in, const int* in_sizes, int n_in,
                              void* d_out, int out_size) {
    const float* coords = (const float*)d_in[0];
    const void* types = d_in[1];
    int N = in_sizes[1];
    int B = (N + PER_BLOCK - 1) / PER_BLOCK;
    float* out = (float*)d_out;
    long long coordsOut = (long long)3 * N;
    int writeTail = ((long long)out_size >= coordsOut + 2 * TT) ? 1 : 0;

    const int SMEM = 98048;
    cudaFuncSetAttribute(k_scatter, cudaFuncAttributeMaxDynamicSharedMemorySize, SMEM);

    k_histscan<<<B, THREADS>>>(types, N, B, out + coordsOut, writeTail);
    k_scatter<<<B, THREADS, SMEM>>>(coords, types, out, N);
}